// round 11
// baseline (speedup 1.0000x reference)
#include <cuda_runtime.h>
#include <cuda_bf16.h>
#include <cstdint>

// ---------------------------------------------------------------------------
// Problem constants
// ---------------------------------------------------------------------------
#define BATCH   32768
#define IN_DIM  1024
#define XROW    3072      // x row stride (3*32*32)
#define EMBED   16
#define TINY    16
#define NEXP    4
#define OUTD    1000
#define KC      72        // padded K for the big GEMM (64 hg + 4 gate + 4 zero)
#define NPAD    1008      // 1000 padded to multiple of 144

// Scratch (device globals — no allocations allowed)
__device__ __align__(16) float g_A[BATCH * KC];        // 9.4 MB  A matrix (tf32-rounded fp32)
__device__ __align__(16) float g_Wc[KC * NPAD];        // 290 KB  combined W2|b2 matrix

// ---------------------------------------------------------------------------
// Helpers
// ---------------------------------------------------------------------------
__device__ __forceinline__ float tf32r(float v) {
    unsigned u;
    asm("cvt.rna.tf32.f32 %0, %1;" : "=r"(u) : "f"(v));
    return __uint_as_float(u);
}

__device__ __forceinline__ void ffma2(unsigned long long& acc,
                                      unsigned long long a,
                                      unsigned long long b) {
    asm("fma.rn.f32x2 %0, %1, %2, %0;" : "+l"(acc) : "l"(a), "l"(b));
}

__device__ __forceinline__ void mma_tf32(float* c, const unsigned* a,
                                         unsigned b0, unsigned b1) {
    asm volatile(
        "mma.sync.aligned.m16n8k8.row.col.f32.tf32.tf32.f32 "
        "{%0,%1,%2,%3}, {%4,%5,%6,%7}, {%8,%9}, {%0,%1,%2,%3};"
        : "+f"(c[0]), "+f"(c[1]), "+f"(c[2]), "+f"(c[3])
        : "r"(a[0]), "r"(a[1]), "r"(a[2]), "r"(a[3]), "r"(b0), "r"(b1));
}

// ---------------------------------------------------------------------------
// Kernel 0: build Wc[72][1008] = [W2 (64 rows) | b2 (4 rows) | zeros], tf32-rounded
// W2 is [4][16][1000] row-major => flattened it is exactly [64][1000].
// ---------------------------------------------------------------------------
__global__ void k_prep(const float* __restrict__ W2, const float* __restrict__ b2) {
    int idx = blockIdx.x * 256 + threadIdx.x;
    if (idx >= KC * NPAD) return;
    int k = idx / NPAD, n = idx % NPAD;
    float v = 0.f;
    if (n < OUTD) {
        if (k < 64)      v = W2[k * OUTD + n];
        else if (k < 68) v = b2[(k - 64) * OUTD + n];
    }
    g_Wc[idx] = tf32r(v);
}

// ---------------------------------------------------------------------------
// Kernel 1: fused embed + gate + experts-hidden.  One thread per batch row.
// Stage 1 in exact fp32 with packed f32x2 FMAs; W_embed cached in smem;
// x staged through smem in 32-col chunks with register prefetch (double buffer).
// Epilogue computes gate softmax + h, writes A row (72 floats, tf32-rounded).
// ---------------------------------------------------------------------------
#define K1_SMEM_FLOATS (16384 /*Wemb*/ + 256*36 /*x chunk*/ + 1024 + 64 + 64 + 16 + 4)

__global__ void __launch_bounds__(256)
k_embed(const float* __restrict__ x,
        const float* __restrict__ We, const float* __restrict__ be,
        const float* __restrict__ W1, const float* __restrict__ b1,
        const float* __restrict__ Wg, const float* __restrict__ bg) {
    extern __shared__ float sm[];
    float* wsf  = sm;                 // W_embed as [16][1024] (== [16][256] float4)
    float* xs   = sm + 16384;         // [256][36]  (pad 36 => conflict-free)
    float* sW1  = xs + 256 * 36;      // [4][16][16]
    float* sWg  = sW1 + 1024;         // [4][16]
    float* sb1  = sWg + 64;           // [4][16]
    float* sbe  = sb1 + 64;           // [16]
    float* sbg  = sbe + 16;           // [4]

    const int tid = threadIdx.x;

    // small copies
    for (int i = tid; i < 1024; i += 256) sW1[i] = W1[i];
    if (tid < 64) sWg[tid] = Wg[tid];
    if (tid < 64) sb1[tid] = b1[tid];
    if (tid < 16) sbe[tid] = be[tid];
    if (tid < 4)  sbg[tid] = bg[tid];
    // W_embed: 16*1024 floats = 4096 float4, same linear layout as global
    {
        const float4* src = (const float4*)We;
        float4* dst = (float4*)wsf;
        for (int i = tid; i < 4096; i += 256) dst[i] = src[i];
    }

    const float* xbase = x + (size_t)blockIdx.x * 256 * XROW;

    // prefetch chunk 0 into registers (coalesced: 8 lanes cover one 128B row seg)
    float4 pre[8];
#pragma unroll
    for (int i = 0; i < 8; i++) {
        int idx = i * 256 + tid;
        int r = idx >> 3, c4 = idx & 7;
        pre[i] = *(const float4*)(xbase + (size_t)r * XROW + c4 * 4);
    }

    unsigned long long acc[EMBED];
#pragma unroll
    for (int j = 0; j < EMBED; j++) acc[j] = 0ull;

    __syncthreads();   // smem weight copies ready

    for (int kc = 0; kc < 32; kc++) {
        // store prefetched chunk
#pragma unroll
        for (int i = 0; i < 8; i++) {
            int idx = i * 256 + tid;
            int r = idx >> 3, c4 = idx & 7;
            *(float4*)(xs + r * 36 + c4 * 4) = pre[i];
        }
        __syncthreads();
        // prefetch next chunk
        if (kc + 1 < 32) {
#pragma unroll
            for (int i = 0; i < 8; i++) {
                int idx = i * 256 + tid;
                int r = idx >> 3, c4 = idx & 7;
                pre[i] = *(const float4*)(xbase + (size_t)r * XROW + (kc + 1) * 32 + c4 * 4);
            }
        }
        // compute: this thread's row = tid (local)
        const ulonglong2* myx = (const ulonglong2*)(xs + tid * 36);
        const ulonglong2* w2p = (const ulonglong2*)wsf;
#pragma unroll
        for (int c4 = 0; c4 < 8; c4++) {
            ulonglong2 xv = myx[c4];
#pragma unroll
            for (int j = 0; j < EMBED; j++) {
                ulonglong2 wv = w2p[j * 256 + kc * 8 + c4];   // broadcast LDS.128
                ffma2(acc[j], xv.x, wv.x);
                ffma2(acc[j], xv.y, wv.y);
            }
        }
        __syncthreads();
    }

    // ---- epilogue (per row) ----
    float e[EMBED];
#pragma unroll
    for (int j = 0; j < EMBED; j++) {
        float lo, hi;
        asm("mov.b64 {%0,%1}, %2;" : "=f"(lo), "=f"(hi) : "l"(acc[j]));
        float v = lo + hi + sbe[j];
        e[j] = v > 0.f ? v : 0.f;
    }
    // gate
    float g[NEXP];
#pragma unroll
    for (int ex = 0; ex < NEXP; ex++) {
        float s = sbg[ex];
#pragma unroll
        for (int j = 0; j < EMBED; j++) s += e[j] * sWg[ex * EMBED + j];
        g[ex] = s;
    }
    float mx = fmaxf(fmaxf(g[0], g[1]), fmaxf(g[2], g[3]));
    float den = 0.f;
#pragma unroll
    for (int ex = 0; ex < NEXP; ex++) { g[ex] = __expf(g[ex] - mx); den += g[ex]; }
    float inv = 1.0f / den;
#pragma unroll
    for (int ex = 0; ex < NEXP; ex++) g[ex] *= inv;

    // experts hidden, gated, write A row
    int row = blockIdx.x * 256 + tid;
    float* Arow = g_A + (size_t)row * KC;
#pragma unroll
    for (int ex = 0; ex < NEXP; ex++) {
#pragma unroll
        for (int t = 0; t < TINY; t++) {
            float s = sb1[ex * TINY + t];
#pragma unroll
            for (int j = 0; j < EMBED; j++)
                s += e[j] * sW1[(ex * EMBED + j) * TINY + t];
            s = s > 0.f ? s : 0.f;
            Arow[ex * TINY + t] = tf32r(s * g[ex]);
        }
        Arow[64 + ex] = tf32r(g[ex]);
    }
    Arow[68] = 0.f; Arow[69] = 0.f; Arow[70] = 0.f; Arow[71] = 0.f;
}

// ---------------------------------------------------------------------------
// Kernel 2: out[32768,1000] = A[32768,72] @ Wc[72,1008]  (tf32 mma, fp32 accum)
// CTA: 256 threads = 8 warps (4 M-groups x 2 N-groups). Tile M=128, N=144.
// Both tiles staged in smem with conflict-free padded strides (A:76, W:152).
// ---------------------------------------------------------------------------
#define K2_SMEM_FLOATS (72 * 152 + 128 * 76)

__global__ void __launch_bounds__(256)
k_gemm(float* __restrict__ out) {
    extern __shared__ float sm[];
    float* Ws = sm;               // [72][152]
    float* As = sm + 72 * 152;    // [128][76]

    const int tid = threadIdx.x;
    const int mb = blockIdx.x, nb = blockIdx.y;

    // W tile: 72 rows x 144 cols
    for (int i = tid; i < 72 * 36; i += 256) {
        int r = i / 36, c4 = i % 36;
        float4 v = *(const float4*)(g_Wc + r * NPAD + nb * 144 + c4 * 4);
        *(float4*)(Ws + r * 152 + c4 * 4) = v;
    }
    // A tile: 128 rows x 72 cols
    for (int i = tid; i < 128 * 18; i += 256) {
        int r = i / 18, c4 = i % 18;
        float4 v = *(const float4*)(g_A + ((size_t)(mb * 128 + r)) * KC + c4 * 4);
        *(float4*)(As + r * 76 + c4 * 4) = v;
    }
    __syncthreads();

    const int wid = tid >> 5, lane = tid & 31;
    const int wm = wid & 3, wn = wid >> 2;
    const int mbase = wm * 32, nbase = wn * 72;
    const int tig = lane & 3, grp = lane >> 2;

    float c[2][9][4];
#pragma unroll
    for (int m = 0; m < 2; m++)
#pragma unroll
        for (int n = 0; n < 9; n++)
#pragma unroll
            for (int q = 0; q < 4; q++) c[m][n][q] = 0.f;

#pragma unroll
    for (int k8 = 0; k8 < 9; k8++) {
        const int k0 = k8 * 8 + tig;
        unsigned a[2][4];
#pragma unroll
        for (int m = 0; m < 2; m++) {
            int r = mbase + m * 16 + grp;
            a[m][0] = __float_as_uint(As[r * 76 + k0]);
            a[m][1] = __float_as_uint(As[(r + 8) * 76 + k0]);
            a[m][2] = __float_as_uint(As[r * 76 + k0 + 4]);
            a[m][3] = __float_as_uint(As[(r + 8) * 76 + k0 + 4]);
        }
#pragma unroll
        for (int n8 = 0; n8 < 9; n8++) {
            int nc = nbase + n8 * 8 + grp;
            unsigned b0 = __float_as_uint(Ws[k0 * 152 + nc]);
            unsigned b1 = __float_as_uint(Ws[(k0 + 4) * 152 + nc]);
            mma_tf32(c[0][n8], a[0], b0, b1);
            mma_tf32(c[1][n8], a[1], b0, b1);
        }
    }

    // epilogue: predicated float2 stores (gc even; 1000 even => pairs all-or-none)
#pragma unroll
    for (int m = 0; m < 2; m++) {
        int gr = mb * 128 + mbase + m * 16 + grp;
#pragma unroll
        for (int n8 = 0; n8 < 9; n8++) {
            int gc = nb * 144 + nbase + n8 * 8 + 2 * tig;
            if (gc < OUTD) {
                *(float2*)(out + (size_t)gr * OUTD + gc) =
                    make_float2(c[m][n8][0], c[m][n8][1]);
                *(float2*)(out + (size_t)(gr + 8) * OUTD + gc) =
                    make_float2(c[m][n8][2], c[m][n8][3]);
            }
        }
    }
}

// ---------------------------------------------------------------------------
// Launch
// ---------------------------------------------------------------------------
extern "C" void kernel_launch(void* const* d_in, const int* in_sizes, int n_in,
                              void* d_out, int out_size) {
    const float* x   = (const float*)d_in[0];
    const float* We  = (const float*)d_in[1];
    const float* be  = (const float*)d_in[2];
    const float* W1  = (const float*)d_in[3];
    const float* b1  = (const float*)d_in[4];
    const float* W2  = (const float*)d_in[5];
    const float* b2  = (const float*)d_in[6];
    const float* Wg  = (const float*)d_in[7];
    const float* bg  = (const float*)d_in[8];
    float* out = (float*)d_out;

    static bool attr_done = false;  // attribute setting only; deterministic & idempotent
    if (!attr_done) {
        cudaFuncSetAttribute(k_embed, cudaFuncAttributeMaxDynamicSharedMemorySize,
                             K1_SMEM_FLOATS * 4);
        cudaFuncSetAttribute(k_gemm, cudaFuncAttributeMaxDynamicSharedMemorySize,
                             K2_SMEM_FLOATS * 4);
        attr_done = true;
    }

    k_prep<<<(KC * NPAD + 255) / 256, 256>>>(W2, b2);
    k_embed<<<BATCH / 256, 256, K1_SMEM_FLOATS * 4>>>(x, We, be, W1, b1, Wg, bg);
    k_gemm<<<dim3(BATCH / 128, NPAD / 144), 256, K2_SMEM_FLOATS * 4>>>(out);
}

// round 12
// speedup vs baseline: 1.1519x; 1.1519x over previous
#include <cuda_runtime.h>
#include <cuda_bf16.h>
#include <cstdint>

// ---------------------------------------------------------------------------
// Problem constants
// ---------------------------------------------------------------------------
#define BATCH   32768
#define IN_DIM  1024
#define XROW    3072      // x row stride (3*32*32)
#define EMBED   16
#define TINY    16
#define NEXP    4
#define OUTD    1000
#define KC      72        // padded K for the big GEMM (64 hg + 4 gate + 4 zero)
#define NPAD    1008      // 1000 padded to multiple of 144

// Scratch (device global — no allocations allowed)
__device__ __align__(16) float g_A[BATCH * KC];   // 9.4 MB  A matrix (tf32-rounded)

// ---------------------------------------------------------------------------
// Helpers
// ---------------------------------------------------------------------------
__device__ __forceinline__ float tf32r(float v) {
    unsigned u;
    asm("cvt.rna.tf32.f32 %0, %1;" : "=r"(u) : "f"(v));
    return __uint_as_float(u);
}

__device__ __forceinline__ void ffma2(unsigned long long& acc,
                                      unsigned long long a,
                                      unsigned long long b) {
    asm("fma.rn.f32x2 %0, %1, %2, %0;" : "+l"(acc) : "l"(a), "l"(b));
}

__device__ __forceinline__ void mma_tf32(float* c, const unsigned* a,
                                         unsigned b0, unsigned b1) {
    asm volatile(
        "mma.sync.aligned.m16n8k8.row.col.f32.tf32.tf32.f32 "
        "{%0,%1,%2,%3}, {%4,%5,%6,%7}, {%8,%9}, {%0,%1,%2,%3};"
        : "+f"(c[0]), "+f"(c[1]), "+f"(c[2]), "+f"(c[3])
        : "r"(a[0]), "r"(a[1]), "r"(a[2]), "r"(a[3]), "r"(b0), "r"(b1));
}

// ---------------------------------------------------------------------------
// Kernel 1: embed via tf32 mma + gate + experts-hidden.  128 rows per CTA,
// 256 threads (8 warps, each owns a 16-row m-tile, N=16 = 2 n-tiles).
// x streamed through double-buffered smem chunks of K=32 (tf32-rounded);
// W_embed tf32 in smem [16][1028] (stride => conflict-free B fragments).
// Epilogue: C -> smem e-tile -> per-row gate softmax + experts (f32x2) -> g_A.
// ---------------------------------------------------------------------------
#define K1_SMEM_FLOATS (16448 /*Wemb [16][1028]*/ + 9216 /*x 2x[128][36]*/ \
                        + 1024 + 64 + 64 + 16 + 4)

__global__ void __launch_bounds__(256, 2)
k_embed(const float* __restrict__ x,
        const float* __restrict__ We, const float* __restrict__ be,
        const float* __restrict__ W1, const float* __restrict__ b1,
        const float* __restrict__ Wg, const float* __restrict__ bg) {
    extern __shared__ float sm[];
    float* Ws  = sm;                    // [16][1028] tf32 W_embed
    float* xb  = sm + 16448;            // 2 x [128][36]  (reused as e-tile later)
    float* sW1 = sm + 16448 + 9216;     // [4][16][16]
    float* sWg = sW1 + 1024;            // [4][16]
    float* sb1 = sWg + 64;              // [4][16]
    float* sbe = sb1 + 64;              // [16]
    float* sbg = sbe + 16;              // [4]

    const int tid = threadIdx.x;

    // small weights
    for (int i = tid; i < 1024; i += 256) sW1[i] = W1[i];
    if (tid < 64)       sWg[tid] = Wg[tid];
    else if (tid < 128) sb1[tid - 64] = b1[tid - 64];
    else if (tid < 144) sbe[tid - 128] = be[tid - 128];
    else if (tid < 148) sbg[tid - 144] = bg[tid - 144];

    // W_embed -> smem [16][1028], tf32-rounded
    for (int i = tid; i < 4096; i += 256) {
        float4 v = ((const float4*)We)[i];
        v.x = tf32r(v.x); v.y = tf32r(v.y); v.z = tf32r(v.z); v.w = tf32r(v.w);
        int row = i >> 8, c4 = i & 255;
        *(float4*)(Ws + row * 1028 + c4 * 4) = v;
    }

    const float* xbase = x + (size_t)blockIdx.x * 128 * XROW;

    // prefetch chunk 0 (coalesced: 8 lanes cover one 128B row segment)
    float4 pre[4];
#pragma unroll
    for (int i = 0; i < 4; i++) {
        int idx = i * 256 + tid;
        int r = idx >> 3, c4 = idx & 7;
        pre[i] = *(const float4*)(xbase + (size_t)r * XROW + c4 * 4);
    }

    const int wid = tid >> 5, lane = tid & 31;
    const int tig = lane & 3, grp = lane >> 2;
    const int arow0 = wid * 16 + grp;

    float c[2][4];
#pragma unroll
    for (int nt = 0; nt < 2; nt++)
#pragma unroll
        for (int q = 0; q < 4; q++) c[nt][q] = 0.f;

    __syncthreads();    // smem weight copies ready

    for (int kc = 0; kc < 32; kc++) {
        float* xcur = xb + (kc & 1) * 4608;
        // store prefetched chunk (tf32-rounded)
#pragma unroll
        for (int i = 0; i < 4; i++) {
            int idx = i * 256 + tid;
            int r = idx >> 3, c4 = idx & 7;
            float4 v = pre[i];
            v.x = tf32r(v.x); v.y = tf32r(v.y); v.z = tf32r(v.z); v.w = tf32r(v.w);
            *(float4*)(xcur + r * 36 + c4 * 4) = v;
        }
        __syncthreads();
        // prefetch next chunk
        if (kc < 31) {
#pragma unroll
            for (int i = 0; i < 4; i++) {
                int idx = i * 256 + tid;
                int r = idx >> 3, c4 = idx & 7;
                pre[i] = *(const float4*)(xbase + (size_t)r * XROW +
                                          (kc + 1) * 32 + c4 * 4);
            }
        }
        // mma over this 32-wide K chunk
        const unsigned* asu = (const unsigned*)xcur;
        const unsigned* wsu = (const unsigned*)Ws;
#pragma unroll
        for (int k8 = 0; k8 < 4; k8++) {
            int k0 = k8 * 8 + tig;
            unsigned a[4];
            a[0] = asu[arow0 * 36 + k0];
            a[1] = asu[(arow0 + 8) * 36 + k0];
            a[2] = asu[arow0 * 36 + k0 + 4];
            a[3] = asu[(arow0 + 8) * 36 + k0 + 4];
            int kg = kc * 32 + k0;
            {
                unsigned b0 = wsu[grp * 1028 + kg];
                unsigned b1 = wsu[grp * 1028 + kg + 4];
                mma_tf32(c[0], a, b0, b1);
            }
            {
                unsigned b0 = wsu[(8 + grp) * 1028 + kg];
                unsigned b1 = wsu[(8 + grp) * 1028 + kg + 4];
                mma_tf32(c[1], a, b0, b1);
            }
        }
        __syncthreads();
    }

    // C fragments -> e-tile in smem (reuse x buffer), stride 20
    float* es = xb;
#pragma unroll
    for (int nt = 0; nt < 2; nt++) {
        int jb = nt * 8 + 2 * tig;
        *(float2*)(es + arow0 * 20 + jb)       = make_float2(c[nt][0], c[nt][1]);
        *(float2*)(es + (arow0 + 8) * 20 + jb) = make_float2(c[nt][2], c[nt][3]);
    }
    __syncthreads();

    // ---- per-row epilogue: 128 threads, one row each ----
    if (tid < 128) {
        float e[EMBED];
#pragma unroll
        for (int q = 0; q < 4; q++) {
            float4 v = *(float4*)(es + tid * 20 + q * 4);
            e[q * 4 + 0] = fmaxf(v.x + sbe[q * 4 + 0], 0.f);
            e[q * 4 + 1] = fmaxf(v.y + sbe[q * 4 + 1], 0.f);
            e[q * 4 + 2] = fmaxf(v.z + sbe[q * 4 + 2], 0.f);
            e[q * 4 + 3] = fmaxf(v.w + sbe[q * 4 + 3], 0.f);
        }
        // gate softmax
        float g[NEXP];
#pragma unroll
        for (int ex = 0; ex < NEXP; ex++) {
            float s = sbg[ex];
#pragma unroll
            for (int j = 0; j < EMBED; j++) s += e[j] * sWg[ex * EMBED + j];
            g[ex] = s;
        }
        float mx = fmaxf(fmaxf(g[0], g[1]), fmaxf(g[2], g[3]));
        float den = 0.f;
#pragma unroll
        for (int ex = 0; ex < NEXP; ex++) { g[ex] = __expf(g[ex] - mx); den += g[ex]; }
        float inv = 1.0f / den;
#pragma unroll
        for (int ex = 0; ex < NEXP; ex++) g[ex] *= inv;

        int row = blockIdx.x * 128 + tid;
        float* Arow = g_A + (size_t)row * KC;
#pragma unroll
        for (int ex = 0; ex < NEXP; ex++) {
            unsigned long long acc[8];
            const ulonglong2* bp = (const ulonglong2*)(sb1 + ex * TINY);
#pragma unroll
            for (int h = 0; h < 4; h++) {
                ulonglong2 t = bp[h];
                acc[2 * h] = t.x; acc[2 * h + 1] = t.y;
            }
#pragma unroll
            for (int j = 0; j < EMBED; j++) {
                unsigned long long ej2;
                asm("mov.b64 %0, {%1, %1};" : "=l"(ej2) : "f"(e[j]));
                const ulonglong2* wp =
                    (const ulonglong2*)(sW1 + (ex * EMBED + j) * TINY);
#pragma unroll
                for (int h = 0; h < 4; h++) {
                    ulonglong2 w = wp[h];
                    ffma2(acc[2 * h], ej2, w.x);
                    ffma2(acc[2 * h + 1], ej2, w.y);
                }
            }
            float gx = g[ex];
            float o[16];
#pragma unroll
            for (int h = 0; h < 8; h++) {
                float lo, hi;
                asm("mov.b64 {%0,%1}, %2;" : "=f"(lo), "=f"(hi) : "l"(acc[h]));
                o[2 * h]     = tf32r(fmaxf(lo, 0.f) * gx);
                o[2 * h + 1] = tf32r(fmaxf(hi, 0.f) * gx);
            }
#pragma unroll
            for (int q = 0; q < 4; q++)
                *(float4*)(Arow + ex * TINY + q * 4) =
                    make_float4(o[4 * q], o[4 * q + 1], o[4 * q + 2], o[4 * q + 3]);
        }
        *(float4*)(Arow + 64) = make_float4(tf32r(g[0]), tf32r(g[1]),
                                            tf32r(g[2]), tf32r(g[3]));
        *(float4*)(Arow + 68) = make_float4(0.f, 0.f, 0.f, 0.f);
    }
}

// ---------------------------------------------------------------------------
// Kernel 2: out[32768,1000] = A[32768,72] @ Wc[72,1008]  (tf32 mma, fp32 acc)
// Wc rows: 0..63 = W2 flat, 64..67 = b2, 68..71 = 0 — built inline during the
// B-tile smem staging (tf32-rounded).  Tiles: M=128, N=144.
// Boundary is clean: for nb<6 all cols < 1000; for nb=6, c4<34 fully in-range,
// c4>=34 fully out (1000-864 = 34*4) — no straddling float4.
// ---------------------------------------------------------------------------
#define K2_SMEM_FLOATS (72 * 152 + 128 * 76)

__global__ void __launch_bounds__(256)
k_gemm(const float* __restrict__ W2, const float* __restrict__ b2,
       float* __restrict__ out) {
    extern __shared__ float sm[];
    float* Ws = sm;               // [72][152]
    float* As = sm + 72 * 152;    // [128][76]

    const int tid = threadIdx.x;
    const int mb = blockIdx.x, nb = blockIdx.y;

    // W tile: 72 rows x 144 cols, built from W2/b2 inline, tf32-rounded
    for (int i = tid; i < 72 * 36; i += 256) {
        int r = i / 36, c4 = i % 36;
        int col = nb * 144 + c4 * 4;
        float4 v = make_float4(0.f, 0.f, 0.f, 0.f);
        if (col < OUTD) {
            if (r < 64)      v = *(const float4*)(W2 + r * OUTD + col);
            else if (r < 68) v = *(const float4*)(b2 + (r - 64) * OUTD + col);
        }
        v.x = tf32r(v.x); v.y = tf32r(v.y); v.z = tf32r(v.z); v.w = tf32r(v.w);
        *(float4*)(Ws + r * 152 + c4 * 4) = v;
    }
    // A tile: 128 rows x 72 cols
    for (int i = tid; i < 128 * 18; i += 256) {
        int r = i / 18, c4 = i % 18;
        float4 v = *(const float4*)(g_A + ((size_t)(mb * 128 + r)) * KC + c4 * 4);
        *(float4*)(As + r * 76 + c4 * 4) = v;
    }
    __syncthreads();

    const int wid = tid >> 5, lane = tid & 31;
    const int wm = wid & 3, wn = wid >> 2;
    const int mbase = wm * 32, nbase = wn * 72;
    const int tig = lane & 3, grp = lane >> 2;

    float c[2][9][4];
#pragma unroll
    for (int m = 0; m < 2; m++)
#pragma unroll
        for (int n = 0; n < 9; n++)
#pragma unroll
            for (int q = 0; q < 4; q++) c[m][n][q] = 0.f;

#pragma unroll
    for (int k8 = 0; k8 < 9; k8++) {
        const int k0 = k8 * 8 + tig;
        unsigned a[2][4];
#pragma unroll
        for (int m = 0; m < 2; m++) {
            int r = mbase + m * 16 + grp;
            a[m][0] = __float_as_uint(As[r * 76 + k0]);
            a[m][1] = __float_as_uint(As[(r + 8) * 76 + k0]);
            a[m][2] = __float_as_uint(As[r * 76 + k0 + 4]);
            a[m][3] = __float_as_uint(As[(r + 8) * 76 + k0 + 4]);
        }
#pragma unroll
        for (int n8 = 0; n8 < 9; n8++) {
            int nc = nbase + n8 * 8 + grp;
            unsigned b0 = __float_as_uint(Ws[k0 * 152 + nc]);
            unsigned b1 = __float_as_uint(Ws[(k0 + 4) * 152 + nc]);
            mma_tf32(c[0][n8], a[0], b0, b1);
            mma_tf32(c[1][n8], a[1], b0, b1);
        }
    }

    // epilogue: predicated float2 stores (gc even; 1000 even => pairs all-or-none)
#pragma unroll
    for (int m = 0; m < 2; m++) {
        int gr = mb * 128 + mbase + m * 16 + grp;
#pragma unroll
        for (int n8 = 0; n8 < 9; n8++) {
            int gc = nb * 144 + nbase + n8 * 8 + 2 * tig;
            if (gc < OUTD) {
                *(float2*)(out + (size_t)gr * OUTD + gc) =
                    make_float2(c[m][n8][0], c[m][n8][1]);
                *(float2*)(out + (size_t)(gr + 8) * OUTD + gc) =
                    make_float2(c[m][n8][2], c[m][n8][3]);
            }
        }
    }
}

// ---------------------------------------------------------------------------
// Launch
// ---------------------------------------------------------------------------
extern "C" void kernel_launch(void* const* d_in, const int* in_sizes, int n_in,
                              void* d_out, int out_size) {
    const float* x   = (const float*)d_in[0];
    const float* We  = (const float*)d_in[1];
    const float* be  = (const float*)d_in[2];
    const float* W1  = (const float*)d_in[3];
    const float* b1  = (const float*)d_in[4];
    const float* W2  = (const float*)d_in[5];
    const float* b2  = (const float*)d_in[6];
    const float* Wg  = (const float*)d_in[7];
    const float* bg  = (const float*)d_in[8];
    float* out = (float*)d_out;

    static bool attr_done = false;  // attribute setting only; deterministic & idempotent
    if (!attr_done) {
        cudaFuncSetAttribute(k_embed, cudaFuncAttributeMaxDynamicSharedMemorySize,
                             K1_SMEM_FLOATS * 4);
        cudaFuncSetAttribute(k_gemm, cudaFuncAttributeMaxDynamicSharedMemorySize,
                             K2_SMEM_FLOATS * 4);
        attr_done = true;
    }

    k_embed<<<BATCH / 128, 256, K1_SMEM_FLOATS * 4>>>(x, We, be, W1, b1, Wg, bg);
    k_gemm<<<dim3(BATCH / 128, NPAD / 144), 256, K2_SMEM_FLOATS * 4>>>(W2, b2, out);
}

// round 13
// speedup vs baseline: 1.5825x; 1.3738x over previous
#include <cuda_runtime.h>
#include <cuda_bf16.h>
#include <cstdint>

// ---------------------------------------------------------------------------
// Problem constants
// ---------------------------------------------------------------------------
#define BATCH   32768
#define IN_DIM  1024
#define XROW    3072      // x row stride (3*32*32)
#define EMBED   16
#define TINY    16
#define NEXP    4
#define OUTD    1000
#define KC      72        // padded K for the big GEMM (64 hg + 4 gate + 4 zero)

// Scratch (device global — no allocations allowed)
__device__ __align__(16) float g_A[BATCH * KC];   // 9.4 MB  A matrix (tf32-rounded)

// ---------------------------------------------------------------------------
// Helpers
// ---------------------------------------------------------------------------
__device__ __forceinline__ float tf32r(float v) {
    unsigned u;
    asm("cvt.rna.tf32.f32 %0, %1;" : "=r"(u) : "f"(v));
    return __uint_as_float(u);
}

__device__ __forceinline__ void ffma2(unsigned long long& acc,
                                      unsigned long long a,
                                      unsigned long long b) {
    asm("fma.rn.f32x2 %0, %1, %2, %0;" : "+l"(acc) : "l"(a), "l"(b));
}

__device__ __forceinline__ void mma_tf32(float* c, const unsigned* a,
                                         unsigned b0, unsigned b1) {
    asm volatile(
        "mma.sync.aligned.m16n8k8.row.col.f32.tf32.tf32.f32 "
        "{%0,%1,%2,%3}, {%4,%5,%6,%7}, {%8,%9}, {%0,%1,%2,%3};"
        : "+f"(c[0]), "+f"(c[1]), "+f"(c[2]), "+f"(c[3])
        : "r"(a[0]), "r"(a[1]), "r"(a[2]), "r"(a[3]), "r"(b0), "r"(b1));
}

__device__ __forceinline__ void cp_async16(void* s, const void* g) {
    unsigned sa = (unsigned)__cvta_generic_to_shared(s);
    asm volatile("cp.async.ca.shared.global [%0], [%1], 16;" :: "r"(sa), "l"(g));
}

// ---------------------------------------------------------------------------
// Kernel 1: embed via tf32 mma + gate + experts-hidden.  128 rows per CTA,
// 256 threads (8 warps, each owns a 16-row m-tile, N=16 = 2 n-tiles).
// x streamed through double-buffered smem chunks of K=32 with a TWO-chunk-deep
// register prefetch (preA/preB ping-pong) so DRAM loads stay in flight across
// the store+sync+compute window.
// ---------------------------------------------------------------------------
#define K1_SMEM_FLOATS (16448 /*Wemb [16][1028]*/ + 9216 /*x 2x[128][36]*/ \
                        + 1024 + 64 + 64 + 16 + 4)

struct K1Ctx {
    float* xb;
    const float* xbase;
    const unsigned* wsu;
    int tid, arow0, tig, grp;
};

__device__ __forceinline__ void k1_step(const K1Ctx& cx, int kc,
                                        float4 (&pre)[4], float (&c)[2][4]) {
    float* xcur = cx.xb + (kc & 1) * 4608;
    // store prefetched chunk (tf32-rounded)
#pragma unroll
    for (int i = 0; i < 4; i++) {
        int idx = i * 256 + cx.tid;
        int r = idx >> 3, c4 = idx & 7;
        float4 v = pre[i];
        v.x = tf32r(v.x); v.y = tf32r(v.y); v.z = tf32r(v.z); v.w = tf32r(v.w);
        *(float4*)(xcur + r * 36 + c4 * 4) = v;
    }
    // refill this buffer with chunk kc+2 (keeps 2 chunks of LDG in flight)
    if (kc + 2 < 32) {
#pragma unroll
        for (int i = 0; i < 4; i++) {
            int idx = i * 256 + cx.tid;
            int r = idx >> 3, c4 = idx & 7;
            pre[i] = *(const float4*)(cx.xbase + (size_t)r * XROW +
                                      (kc + 2) * 32 + c4 * 4);
        }
    }
    __syncthreads();
    // mma over this 32-wide K chunk
    const unsigned* asu = (const unsigned*)xcur;
#pragma unroll
    for (int k8 = 0; k8 < 4; k8++) {
        int k0 = k8 * 8 + cx.tig;
        unsigned a[4];
        a[0] = asu[cx.arow0 * 36 + k0];
        a[1] = asu[(cx.arow0 + 8) * 36 + k0];
        a[2] = asu[cx.arow0 * 36 + k0 + 4];
        a[3] = asu[(cx.arow0 + 8) * 36 + k0 + 4];
        int kg = kc * 32 + k0;
        {
            unsigned b0 = cx.wsu[cx.grp * 1028 + kg];
            unsigned b1 = cx.wsu[cx.grp * 1028 + kg + 4];
            mma_tf32(c[0], a, b0, b1);
        }
        {
            unsigned b0 = cx.wsu[(8 + cx.grp) * 1028 + kg];
            unsigned b1 = cx.wsu[(8 + cx.grp) * 1028 + kg + 4];
            mma_tf32(c[1], a, b0, b1);
        }
    }
    __syncthreads();
}

__global__ void __launch_bounds__(256, 2)
k_embed(const float* __restrict__ x,
        const float* __restrict__ We, const float* __restrict__ be,
        const float* __restrict__ W1, const float* __restrict__ b1,
        const float* __restrict__ Wg, const float* __restrict__ bg) {
    extern __shared__ float sm[];
    float* Ws  = sm;                    // [16][1028] tf32 W_embed
    float* xb  = sm + 16448;            // 2 x [128][36]  (reused as e-tile later)
    float* sW1 = sm + 16448 + 9216;     // [4][16][16]
    float* sWg = sW1 + 1024;            // [4][16]
    float* sb1 = sWg + 64;              // [4][16]
    float* sbe = sb1 + 64;              // [16]
    float* sbg = sbe + 16;              // [4]

    const int tid = threadIdx.x;
    const float* xbase = x + (size_t)blockIdx.x * 128 * XROW;

    // 2-deep register prefetch of x chunks 0 and 1 (issued first: longest latency)
    float4 preA[4], preB[4];
#pragma unroll
    for (int i = 0; i < 4; i++) {
        int idx = i * 256 + tid;
        int r = idx >> 3, c4 = idx & 7;
        preA[i] = *(const float4*)(xbase + (size_t)r * XROW + c4 * 4);
    }
#pragma unroll
    for (int i = 0; i < 4; i++) {
        int idx = i * 256 + tid;
        int r = idx >> 3, c4 = idx & 7;
        preB[i] = *(const float4*)(xbase + (size_t)r * XROW + 32 + c4 * 4);
    }

    // small weights
    for (int i = tid; i < 1024; i += 256) sW1[i] = W1[i];
    if (tid < 64)       sWg[tid] = Wg[tid];
    else if (tid < 128) sb1[tid - 64] = b1[tid - 64];
    else if (tid < 144) sbe[tid - 128] = be[tid - 128];
    else if (tid < 148) sbg[tid - 144] = bg[tid - 144];

    // W_embed -> smem [16][1028], tf32-rounded
    for (int i = tid; i < 4096; i += 256) {
        float4 v = ((const float4*)We)[i];
        v.x = tf32r(v.x); v.y = tf32r(v.y); v.z = tf32r(v.z); v.w = tf32r(v.w);
        int row = i >> 8, c4 = i & 255;
        *(float4*)(Ws + row * 1028 + c4 * 4) = v;
    }

    const int wid = tid >> 5, lane = tid & 31;
    const int tig = lane & 3, grp = lane >> 2;

    K1Ctx cx;
    cx.xb = xb; cx.xbase = xbase; cx.wsu = (const unsigned*)Ws;
    cx.tid = tid; cx.arow0 = wid * 16 + grp; cx.tig = tig; cx.grp = grp;

    float c[2][4];
#pragma unroll
    for (int nt = 0; nt < 2; nt++)
#pragma unroll
        for (int q = 0; q < 4; q++) c[nt][q] = 0.f;

    __syncthreads();    // smem weight copies ready

    for (int kc = 0; kc < 32; kc += 2) {
        k1_step(cx, kc,     preA, c);
        k1_step(cx, kc + 1, preB, c);
    }

    // C fragments -> e-tile in smem (reuse x buffer), stride 20
    float* es = xb;
    const int arow0 = cx.arow0;
#pragma unroll
    for (int nt = 0; nt < 2; nt++) {
        int jb = nt * 8 + 2 * tig;
        *(float2*)(es + arow0 * 20 + jb)       = make_float2(c[nt][0], c[nt][1]);
        *(float2*)(es + (arow0 + 8) * 20 + jb) = make_float2(c[nt][2], c[nt][3]);
    }
    __syncthreads();

    // ---- per-row epilogue: 128 threads, one row each ----
    if (tid < 128) {
        float e[EMBED];
#pragma unroll
        for (int q = 0; q < 4; q++) {
            float4 v = *(float4*)(es + tid * 20 + q * 4);
            e[q * 4 + 0] = fmaxf(v.x + sbe[q * 4 + 0], 0.f);
            e[q * 4 + 1] = fmaxf(v.y + sbe[q * 4 + 1], 0.f);
            e[q * 4 + 2] = fmaxf(v.z + sbe[q * 4 + 2], 0.f);
            e[q * 4 + 3] = fmaxf(v.w + sbe[q * 4 + 3], 0.f);
        }
        // gate softmax
        float g[NEXP];
#pragma unroll
        for (int ex = 0; ex < NEXP; ex++) {
            float s = sbg[ex];
#pragma unroll
            for (int j = 0; j < EMBED; j++) s += e[j] * sWg[ex * EMBED + j];
            g[ex] = s;
        }
        float mx = fmaxf(fmaxf(g[0], g[1]), fmaxf(g[2], g[3]));
        float den = 0.f;
#pragma unroll
        for (int ex = 0; ex < NEXP; ex++) { g[ex] = __expf(g[ex] - mx); den += g[ex]; }
        float inv = 1.0f / den;
#pragma unroll
        for (int ex = 0; ex < NEXP; ex++) g[ex] *= inv;

        int row = blockIdx.x * 128 + tid;
        float* Arow = g_A + (size_t)row * KC;
#pragma unroll
        for (int ex = 0; ex < NEXP; ex++) {
            unsigned long long acc[8];
            const ulonglong2* bp = (const ulonglong2*)(sb1 + ex * TINY);
#pragma unroll
            for (int h = 0; h < 4; h++) {
                ulonglong2 t = bp[h];
                acc[2 * h] = t.x; acc[2 * h + 1] = t.y;
            }
#pragma unroll
            for (int j = 0; j < EMBED; j++) {
                unsigned long long ej2;
                asm("mov.b64 %0, {%1, %1};" : "=l"(ej2) : "f"(e[j]));
                const ulonglong2* wp =
                    (const ulonglong2*)(sW1 + (ex * EMBED + j) * TINY);
#pragma unroll
                for (int h = 0; h < 4; h++) {
                    ulonglong2 w = wp[h];
                    ffma2(acc[2 * h], ej2, w.x);
                    ffma2(acc[2 * h + 1], ej2, w.y);
                }
            }
            float gx = g[ex];
            float o[16];
#pragma unroll
            for (int h = 0; h < 8; h++) {
                float lo, hi;
                asm("mov.b64 {%0,%1}, %2;" : "=f"(lo), "=f"(hi) : "l"(acc[h]));
                o[2 * h]     = tf32r(fmaxf(lo, 0.f) * gx);
                o[2 * h + 1] = tf32r(fmaxf(hi, 0.f) * gx);
            }
#pragma unroll
            for (int q = 0; q < 4; q++)
                *(float4*)(Arow + ex * TINY + q * 4) =
                    make_float4(o[4 * q], o[4 * q + 1], o[4 * q + 2], o[4 * q + 3]);
        }
        *(float4*)(Arow + 64) = make_float4(tf32r(g[0]), tf32r(g[1]),
                                            tf32r(g[2]), tf32r(g[3]));
        *(float4*)(Arow + 68) = make_float4(0.f, 0.f, 0.f, 0.f);
    }
}

// ---------------------------------------------------------------------------
// Kernel 2: out[32768,1000] = A[32768,72] @ Wc[72,1024]  (tf32 mma, fp32 acc)
// Wc rows: 0..63 = W2 flat, 64..67 = b2, 68..71 = 0 — built inline in smem.
// Tiles: M=128, N=128 (grid 256 x 8).  Accumulators 64 regs =>
// __launch_bounds__(256,2) gives 2 CTAs/SM (RF-limited before), overlapping
// the load / compute / store phases across resident CTAs.
// A tile comes in via cp.async (g_A is already tf32-rounded).
// Boundary: 1000-896 = 26*4 => no float4 straddles the valid-column edge.
// ---------------------------------------------------------------------------
#define K2_SMEM_FLOATS (72 * 136 + 128 * 76)

__global__ void __launch_bounds__(256, 2)
k_gemm(const float* __restrict__ W2, const float* __restrict__ b2,
       float* __restrict__ out) {
    extern __shared__ float sm[];
    float* Ws = sm;               // [72][136]  (stride%32==8 -> conflict-free B)
    float* As = sm + 72 * 136;    // [128][76]

    const int tid = threadIdx.x;
    const int mb = blockIdx.x, nb = blockIdx.y;

    // A tile via cp.async: 128 rows x 18 float4
    {
        const float* Abase = g_A + (size_t)mb * 128 * KC;
#pragma unroll
        for (int i = tid; i < 128 * 18; i += 256) {
            int r = i / 18, c4 = i % 18;
            cp_async16(As + r * 76 + c4 * 4, Abase + r * KC + c4 * 4);
        }
        asm volatile("cp.async.commit_group;");
    }
    // W tile: 72 rows x 128 cols, built from W2/b2 inline, tf32-rounded
    for (int i = tid; i < 72 * 32; i += 256) {
        int r = i / 32, c4 = i % 32;
        int col = nb * 128 + c4 * 4;
        float4 v = make_float4(0.f, 0.f, 0.f, 0.f);
        if (col < OUTD) {
            if (r < 64)      v = *(const float4*)(W2 + r * OUTD + col);
            else if (r < 68) v = *(const float4*)(b2 + (r - 64) * OUTD + col);
        }
        v.x = tf32r(v.x); v.y = tf32r(v.y); v.z = tf32r(v.z); v.w = tf32r(v.w);
        *(float4*)(Ws + r * 136 + c4 * 4) = v;
    }
    asm volatile("cp.async.wait_group 0;");
    __syncthreads();

    const int wid = tid >> 5, lane = tid & 31;
    const int wm = wid & 3, wn = wid >> 2;
    const int mbase = wm * 32, nbase = wn * 64;
    const int tig = lane & 3, grp = lane >> 2;

    float c[2][8][4];
#pragma unroll
    for (int m = 0; m < 2; m++)
#pragma unroll
        for (int n = 0; n < 8; n++)
#pragma unroll
            for (int q = 0; q < 4; q++) c[m][n][q] = 0.f;

#pragma unroll
    for (int k8 = 0; k8 < 9; k8++) {
        const int k0 = k8 * 8 + tig;
        unsigned a[2][4];
#pragma unroll
        for (int m = 0; m < 2; m++) {
            int r = mbase + m * 16 + grp;
            a[m][0] = __float_as_uint(As[r * 76 + k0]);
            a[m][1] = __float_as_uint(As[(r + 8) * 76 + k0]);
            a[m][2] = __float_as_uint(As[r * 76 + k0 + 4]);
            a[m][3] = __float_as_uint(As[(r + 8) * 76 + k0 + 4]);
        }
#pragma unroll
        for (int n8 = 0; n8 < 8; n8++) {
            int nc = nbase + n8 * 8 + grp;
            unsigned b0 = __float_as_uint(Ws[k0 * 136 + nc]);
            unsigned b1 = __float_as_uint(Ws[(k0 + 4) * 136 + nc]);
            mma_tf32(c[0][n8], a[0], b0, b1);
            mma_tf32(c[1][n8], a[1], b0, b1);
        }
    }

    // epilogue: predicated float2 stores (gc even; 1000 even => pairs all-or-none)
#pragma unroll
    for (int m = 0; m < 2; m++) {
        int gr = mb * 128 + mbase + m * 16 + grp;
#pragma unroll
        for (int n8 = 0; n8 < 8; n8++) {
            int gc = nb * 128 + nbase + n8 * 8 + 2 * tig;
            if (gc < OUTD) {
                *(float2*)(out + (size_t)gr * OUTD + gc) =
                    make_float2(c[m][n8][0], c[m][n8][1]);
                *(float2*)(out + (size_t)(gr + 8) * OUTD + gc) =
                    make_float2(c[m][n8][2], c[m][n8][3]);
            }
        }
    }
}

// ---------------------------------------------------------------------------
// Launch
// ---------------------------------------------------------------------------
extern "C" void kernel_launch(void* const* d_in, const int* in_sizes, int n_in,
                              void* d_out, int out_size) {
    const float* x   = (const float*)d_in[0];
    const float* We  = (const float*)d_in[1];
    const float* be  = (const float*)d_in[2];
    const float* W1  = (const float*)d_in[3];
    const float* b1  = (const float*)d_in[4];
    const float* W2  = (const float*)d_in[5];
    const float* b2  = (const float*)d_in[6];
    const float* Wg  = (const float*)d_in[7];
    const float* bg  = (const float*)d_in[8];
    float* out = (float*)d_out;

    static bool attr_done = false;  // attribute setting only; deterministic & idempotent
    if (!attr_done) {
        cudaFuncSetAttribute(k_embed, cudaFuncAttributeMaxDynamicSharedMemorySize,
                             K1_SMEM_FLOATS * 4);
        cudaFuncSetAttribute(k_gemm, cudaFuncAttributeMaxDynamicSharedMemorySize,
                             K2_SMEM_FLOATS * 4);
        attr_done = true;
    }

    k_embed<<<BATCH / 128, 256, K1_SMEM_FLOATS * 4>>>(x, We, be, W1, b1, Wg, bg);
    k_gemm<<<dim3(BATCH / 128, 8), 256, K2_SMEM_FLOATS * 4>>>(W2, b2, out);
}